// round 12
// baseline (speedup 1.0000x reference)
#include <cuda_runtime.h>
#include <cuda_fp16.h>
#include <cstring>

#define B_    2
#define C_    32
#define H_    128
#define W_    256
#define MAXD  12
#define D_    23            // 2*MAXD - 1
#define HW    (H_ * W_)
#define WT    128           // threads per CTA (half row)
#define NO    4             // channel octs of 8
#define SW2   220           // window: 76 left halo + 128 + 16 right
#define HALO  76
#define DG    12            // disparities per split (d=11 computed by both)
#define CH    7             // taps per pipeline chunk (A: 0-6, B: 6-12)

__device__ __forceinline__ __half2 u2h2(unsigned u) {
    __half2 r; memcpy(&r, &u, 4); return r;
}

struct Flc { __half2 X, Y, Z, W; };

__device__ __forceinline__ Flc load_flc(const float* __restrict__ fl0, int o) {
    Flc f;
    const float a0 = __ldg(fl0 + (2*o)      * HW);
    const float a1 = __ldg(fl0 + (2*o + 1)  * HW);
    const float a2 = __ldg(fl0 + (2*o + 16) * HW);
    const float a3 = __ldg(fl0 + (2*o + 17) * HW);
    const float b0 = __ldg(fl0 + (2*o + 8)  * HW);
    const float b1 = __ldg(fl0 + (2*o + 9)  * HW);
    const float b2 = __ldg(fl0 + (2*o + 24) * HW);
    const float b3 = __ldg(fl0 + (2*o + 25) * HW);
    f.X = __floats2half2_rn(a0, a2);
    f.Y = __floats2half2_rn(a1, a3);
    f.Z = __floats2half2_rn(b0, b2);
    f.W = __floats2half2_rn(b1, b3);
    return f;
}

__device__ __forceinline__ void load_chunk(uint4* buf, const uint4* src) {
    #pragma unroll
    for (int j = 0; j < CH; j++) buf[j] = src[j];   // 7 x LDS.128
}

// Math for one 7-tap chunk: 6 disparities (hbase = 0 for chunk A, 6 for B).
// Identical op order to R11's d-loop -> bit-identical results.
__device__ __forceinline__ void math_chunk(const uint4* t, int hbase, Flc f,
                                           __half2* acc2,
                                           __half2 nw0, __half2 nw1) {
    #pragma unroll
    for (int dd = 0; dd < 6; dd++) {
        __half2 u0 = __hfma2(u2h2(t[dd].x),     nw0, f.X);
        u0         = __hfma2(u2h2(t[dd + 1].x), nw1, u0);
        __half2 u1 = __hfma2(u2h2(t[dd].y),     nw0, f.Y);
        u1         = __hfma2(u2h2(t[dd + 1].y), nw1, u1);
        __half2 u2 = __hfma2(u2h2(t[dd].z),     nw0, f.Z);
        u2         = __hfma2(u2h2(t[dd + 1].z), nw1, u2);
        __half2 u3 = __hfma2(u2h2(t[dd].w),     nw0, f.W);
        u3         = __hfma2(u2h2(t[dd + 1].w), nw1, u3);
        __half2 s01 = __hadd2(__habs2(u0), __habs2(u1));
        __half2 s23 = __hadd2(__habs2(u2), __habs2(u3));
        acc2[hbase + dd] = __hadd2(acc2[hbase + dd], __hadd2(s01, s23));
    }
}

__device__ __forceinline__ void flush_acc(__half2* acc2, float* accf) {
    #pragma unroll
    for (int d = 0; d < DG; d++) {
        float2 f = __half22float2(acc2[d]);
        accf[d] += f.x + f.y;
        acc2[d] = __float2half2_rn(0.0f);
    }
}

// out[b,d,h,w] = sum_c |feat_l[b,c,h,w] - (w0*fr[c,x0+d] + w1*fr[c,x0+d+1])|
// R11 (fp16 8-channel octs, LDS.128 gather, 1024 thin CTAs) + explicit
// register double-buffering: while chunk s's math runs, chunk s+1's 7 LDS
// are already issued, so the shared-memory crossbar (the measured 55%-busy
// bottleneck that never saturated) is fed continuously instead of in
// per-oct bursts.
__global__ __launch_bounds__(WT)
void cost_volume_kernel(const float* __restrict__ feat_l,
                        const float* __restrict__ feat_r,
                        const float* __restrict__ disp,
                        float* __restrict__ out)
{
    __shared__ __align__(16) uint4 s_o[NO][SW2];   // 14080 B

    const int xb    = blockIdx.x;        // 0..3 : (spl<<1)|half
    const int half_ = xb & 1;
    const int spl   = xb >> 1;
    const int h     = blockIdx.y;
    const int b     = blockIdx.z;
    const int tid   = threadIdx.x;
    const int W0    = half_ * WT;
    const int base  = W0 - HALO;         // global x of window index 0
    const int dlo   = spl * 11;          // 0 or 11

    // ---- stage zero-padded feat_r window as 8-channel octs (R11 fill) ----
    {
        const float* fr0 = feat_r + (((long)b * C_) * H_ + h) * W_;
        #pragma unroll
        for (int s = 0; s < 2; s++) {
            const int i = tid + s * WT;
            if (i < SW2) {
                const int gx = base + i;
                const bool v = (gx >= 0) & (gx < W_);
                const int gxc = v ? gx : 0;
                #pragma unroll
                for (int o = 0; o < NO; o++) {
                    const float a0 = v ? __ldg(fr0 + (2*o)      * HW + gxc) : 0.0f;
                    const float a1 = v ? __ldg(fr0 + (2*o + 1)  * HW + gxc) : 0.0f;
                    const float a2 = v ? __ldg(fr0 + (2*o + 16) * HW + gxc) : 0.0f;
                    const float a3 = v ? __ldg(fr0 + (2*o + 17) * HW + gxc) : 0.0f;
                    const float b0 = v ? __ldg(fr0 + (2*o + 8)  * HW + gxc) : 0.0f;
                    const float b1 = v ? __ldg(fr0 + (2*o + 9)  * HW + gxc) : 0.0f;
                    const float b2 = v ? __ldg(fr0 + (2*o + 24) * HW + gxc) : 0.0f;
                    const float b3 = v ? __ldg(fr0 + (2*o + 25) * HW + gxc) : 0.0f;
                    __half2 px = __floats2half2_rn(a0, a2);
                    __half2 py = __floats2half2_rn(a1, a3);
                    __half2 pz = __floats2half2_rn(b0, b2);
                    __half2 pw = __floats2half2_rn(b1, b3);
                    uint4 ov;
                    memcpy(&ov.x, &px, 4); memcpy(&ov.y, &py, 4);
                    memcpy(&ov.z, &pz, 4); memcpy(&ov.w, &pw, 4);
                    s_o[o][i] = ov;
                }
            }
        }
    }

    // ---- per-thread interpolation setup (overlaps fill) ----
    const int   w    = W0 + tid;
    const float dval = __ldg(disp + ((long)b * H_ + h) * W_ + w);
    const float px0  = ((float)w - dval) - (float)(MAXD - 1);
    const float xf   = floorf(px0);
    const float w1   = px0 - xf;          // right-neighbor weight (const over d)
    const float w0   = 1.0f - w1;
    int x0l = (int)xf - base;             // in [tid+1, tid+65]
    x0l = max(0, min(SW2 - 24, x0l));     // xs + 12 <= 219 for both splits
    const int xs = x0l + dlo;

    const __half2 nw0 = __float2half2_rn(-w0);
    const __half2 nw1 = __float2half2_rn(-w1);

    __syncthreads();

    float accf[DG];
    __half2 acc2[DG];
    #pragma unroll
    for (int d = 0; d < DG; d++) { accf[d] = 0.0f; acc2[d] = __float2half2_rn(0.0f); }

    const float* fl0 = feat_l + (((long)b * C_) * H_ + h) * W_ + w;

    uint4 bA[CH], bB[CH];

    // ---- 8-step software pipeline over 4 octs x 2 chunks ----
    load_chunk(bA, &s_o[0][xs]);                    // A0
    Flc f0 = load_flc(fl0, 0);

    load_chunk(bB, &s_o[0][xs + 6]);                // B0 in flight
    math_chunk(bA, 0, f0, acc2, nw0, nw1);          // math A0

    load_chunk(bA, &s_o[1][xs]);                    // A1 in flight
    Flc f1 = load_flc(fl0, 1);
    math_chunk(bB, 6, f0, acc2, nw0, nw1);          // math B0
    flush_acc(acc2, accf);                          // oct 0 done

    load_chunk(bB, &s_o[1][xs + 6]);                // B1
    math_chunk(bA, 0, f1, acc2, nw0, nw1);          // math A1

    load_chunk(bA, &s_o[2][xs]);                    // A2
    Flc f2 = load_flc(fl0, 2);
    math_chunk(bB, 6, f1, acc2, nw0, nw1);          // math B1
    flush_acc(acc2, accf);                          // oct 1 done

    load_chunk(bB, &s_o[2][xs + 6]);                // B2
    math_chunk(bA, 0, f2, acc2, nw0, nw1);          // math A2

    load_chunk(bA, &s_o[3][xs]);                    // A3
    Flc f3 = load_flc(fl0, 3);
    math_chunk(bB, 6, f2, acc2, nw0, nw1);          // math B2
    flush_acc(acc2, accf);                          // oct 2 done

    load_chunk(bB, &s_o[3][xs + 6]);                // B3
    math_chunk(bA, 0, f3, acc2, nw0, nw1);          // math A3

    math_chunk(bB, 6, f3, acc2, nw0, nw1);          // math B3
    flush_acc(acc2, accf);                          // oct 3 done

    // ---- write out[b, dlo+d, h, w] (d=11 written by both splits, same value) ----
    float* orow = out + (((long)b * D_ + dlo) * H_ + h) * W_ + w;
    #pragma unroll
    for (int d = 0; d < DG; d++)
        orow[(long)d * HW] = accf[d];
}

extern "C" void kernel_launch(void* const* d_in, const int* in_sizes, int n_in,
                              void* d_out, int out_size)
{
    (void)in_sizes; (void)n_in; (void)out_size;
    const float* feat_l = (const float*)d_in[0];
    const float* feat_r = (const float*)d_in[1];
    const float* disp   = (const float*)d_in[2];
    float* out = (float*)d_out;

    dim3 grid(4, H_, B_);     // 2 halves x 2 d-splits = 1024 thin CTAs
    cost_volume_kernel<<<grid, WT>>>(feat_l, feat_r, disp, out);
}

// round 13
// speedup vs baseline: 1.1359x; 1.1359x over previous
#include <cuda_runtime.h>
#include <cuda_fp16.h>
#include <cstring>

#define B_    2
#define C_    32
#define H_    128
#define W_    256
#define MAXD  12
#define D_    23            // 2*MAXD - 1
#define HW    (H_ * W_)
#define WT    128           // threads per CTA (half row)
#define NO    4             // channel octs of 8
#define SW2   220           // window: 76 left halo + 128 + 16 right
#define HALO  76
#define DG    12            // disparities per split (d=11 computed by both)
#define TAPS  13            // DG + 1

__device__ __forceinline__ __half2 u2h2(unsigned u) {
    __half2 r; memcpy(&r, &u, 4); return r;
}

// out[b,d,h,w] = sum_c |feat_l[b,c,h,w] - (w0*fr[c,x0+d] + w1*fr[c,x0+d+1])|
// R11 (fp16 8-channel octs, 13 x LDS.128 gather, 1024 thin CTAs) + a
// WARP-LOCAL residue sort: an LDS.128 runs as 4 subphases of 8 lanes, each
// lane's 16B granule landing in one of 8 slots = (xs & 7). Random xs gives
// E[max 8-in-8] ~ 2.5 -> ~10 cyc/LDS.128 (matches measured 16K L1 cyc/SM).
// Sorting the warp's 32 pixels by (xs & 7) and dealing rank r to lane
// (r>>2)|((r&3)<<3) makes every subphase cover ~distinct slots (~1.4).
// The permutation stays inside the warp, so feat_l/out address SETS are
// unchanged -> no scatter penalty. Math per pixel identical -> bit-identical.
__global__ __launch_bounds__(WT)
void cost_volume_kernel(const float* __restrict__ feat_l,
                        const float* __restrict__ feat_r,
                        const float* __restrict__ disp,
                        float* __restrict__ out)
{
    __shared__ __align__(16) uint4 s_o[NO][SW2];   // 14080 B
    __shared__ int s_src[4][32];                   // warp permutation bounce

    const int xb    = blockIdx.x;        // 0..3 : (spl<<1)|half
    const int half_ = xb & 1;
    const int spl   = xb >> 1;
    const int h     = blockIdx.y;
    const int b     = blockIdx.z;
    const int tid   = threadIdx.x;
    const int lane  = tid & 31;
    const int wid   = tid >> 5;
    const int W0    = half_ * WT;
    const int base  = W0 - HALO;         // global x of window index 0
    const int dlo   = spl * 11;          // 0 or 11

    // ---- stage zero-padded feat_r window as 8-channel octs (R11 fill) ----
    {
        const float* fr0 = feat_r + (((long)b * C_) * H_ + h) * W_;
        #pragma unroll
        for (int s = 0; s < 2; s++) {
            const int i = tid + s * WT;
            if (i < SW2) {
                const int gx = base + i;
                const bool v = (gx >= 0) & (gx < W_);
                const int gxc = v ? gx : 0;
                #pragma unroll
                for (int o = 0; o < NO; o++) {
                    const float a0 = v ? __ldg(fr0 + (2*o)      * HW + gxc) : 0.0f;
                    const float a1 = v ? __ldg(fr0 + (2*o + 1)  * HW + gxc) : 0.0f;
                    const float a2 = v ? __ldg(fr0 + (2*o + 16) * HW + gxc) : 0.0f;
                    const float a3 = v ? __ldg(fr0 + (2*o + 17) * HW + gxc) : 0.0f;
                    const float b0 = v ? __ldg(fr0 + (2*o + 8)  * HW + gxc) : 0.0f;
                    const float b1 = v ? __ldg(fr0 + (2*o + 9)  * HW + gxc) : 0.0f;
                    const float b2 = v ? __ldg(fr0 + (2*o + 24) * HW + gxc) : 0.0f;
                    const float b3 = v ? __ldg(fr0 + (2*o + 25) * HW + gxc) : 0.0f;
                    __half2 px = __floats2half2_rn(a0, a2);
                    __half2 py = __floats2half2_rn(a1, a3);
                    __half2 pz = __floats2half2_rn(b0, b2);
                    __half2 pw = __floats2half2_rn(b1, b3);
                    uint4 ov;
                    memcpy(&ov.x, &px, 4); memcpy(&ov.y, &py, 4);
                    memcpy(&ov.z, &pz, 4); memcpy(&ov.w, &pw, 4);
                    s_o[o][i] = ov;
                }
            }
        }
    }

    // ---- per-thread interpolation setup (own pixel) ----
    const int   wown = W0 + tid;
    const float dval = __ldg(disp + ((long)b * H_ + h) * W_ + wown);
    const float px0  = ((float)wown - dval) - (float)(MAXD - 1);
    const float xf   = floorf(px0);
    float w1own = px0 - xf;
    int x0l = (int)xf - base;
    x0l = max(0, min(SW2 - 24, x0l));
    int xsown = x0l + dlo;

    // ---- warp-local residue-8 sort: deal pixels so each LDS.128 subphase
    //      (8 lanes) covers ~distinct 16B slots ----
    {
        const int key = xsown & 7;
        int lt = 0;
        unsigned eqmask = 0;
        #pragma unroll
        for (int v = 0; v < 8; v++) {
            unsigned bv = __ballot_sync(0xffffffffu, key == v);
            if (v < key) lt += __popc(bv);
            if (v == key) eqmask = bv;
        }
        const int rank = lt + __popc(eqmask & ((1u << lane) - 1u));
        const int dest = (rank >> 2) | ((rank & 3) << 3);   // inverse deal
        s_src[wid][dest] = lane;
        __syncwarp();
        const int m = s_src[wid][lane];
        __syncwarp();
        xsown = __shfl_sync(0xffffffffu, xsown, m);
        w1own = __shfl_sync(0xffffffffu, w1own, m);
    }
    const int   xs = xsown;
    const int   wp = W0 + ((xs - dlo) <= 0 ? 0 : 0); // placeholder (computed below)
    // recover pixel index: shuffle it directly instead
    // (wp computed via shuffle of wown)
    (void)wp;

    // shuffle the pixel coordinate too (same src lane)
    int wpix;
    {
        // m was consumed above; redo the exchange for wown through s_src
        const int m2 = s_src[wid][lane];
        wpix = __shfl_sync(0xffffffffu, wown, m2);
    }

    const float w1 = w1own;
    const float w0 = 1.0f - w1;
    const __half2 nw0 = __float2half2_rn(-w0);
    const __half2 nw1 = __float2half2_rn(-w1);

    __syncthreads();

    float accf[DG];
    #pragma unroll
    for (int d = 0; d < DG; d++) accf[d] = 0.0f;

    const float* fl0 = feat_l + (((long)b * C_) * H_ + h) * W_ + wpix;

    #pragma unroll 1
    for (int o = 0; o < NO; o++) {                 // 4 octs (8 channels each)
        const float a0 = __ldg(fl0 + (2*o)      * HW);
        const float a1 = __ldg(fl0 + (2*o + 1)  * HW);
        const float a2 = __ldg(fl0 + (2*o + 16) * HW);
        const float a3 = __ldg(fl0 + (2*o + 17) * HW);
        const float b0 = __ldg(fl0 + (2*o + 8)  * HW);
        const float b1 = __ldg(fl0 + (2*o + 9)  * HW);
        const float b2 = __ldg(fl0 + (2*o + 24) * HW);
        const float b3 = __ldg(fl0 + (2*o + 25) * HW);
        const __half2 fX = __floats2half2_rn(a0, a2);
        const __half2 fY = __floats2half2_rn(a1, a3);
        const __half2 fZ = __floats2half2_rn(b0, b2);
        const __half2 fW = __floats2half2_rn(b1, b3);

        const uint4* row = &s_o[o][xs];
        uint4 t[TAPS];
        #pragma unroll
        for (int j = 0; j < TAPS; j++) t[j] = row[j];   // 13 x LDS.128

        __half2 acc2[DG];
        #pragma unroll
        for (int d = 0; d < DG; d++) acc2[d] = __float2half2_rn(0.0f);

        #pragma unroll
        for (int d = 0; d < DG; d++) {
            __half2 u0 = __hfma2(u2h2(t[d].x),     nw0, fX);
            u0         = __hfma2(u2h2(t[d + 1].x), nw1, u0);
            __half2 u1 = __hfma2(u2h2(t[d].y),     nw0, fY);
            u1         = __hfma2(u2h2(t[d + 1].y), nw1, u1);
            __half2 u2 = __hfma2(u2h2(t[d].z),     nw0, fZ);
            u2         = __hfma2(u2h2(t[d + 1].z), nw1, u2);
            __half2 u3 = __hfma2(u2h2(t[d].w),     nw0, fW);
            u3         = __hfma2(u2h2(t[d + 1].w), nw1, u3);
            __half2 s01 = __hadd2(__habs2(u0), __habs2(u1));
            __half2 s23 = __hadd2(__habs2(u2), __habs2(u3));
            acc2[d] = __hadd2(acc2[d], __hadd2(s01, s23));
        }

        #pragma unroll
        for (int d = 0; d < DG; d++) {
            float2 f = __half22float2(acc2[d]);
            accf[d] += f.x + f.y;
        }
    }

    // ---- write out[b, dlo+d, h, wpix] (same address set per warp) ----
    float* orow = out + (((long)b * D_ + dlo) * H_ + h) * W_ + wpix;
    #pragma unroll
    for (int d = 0; d < DG; d++)
        orow[(long)d * HW] = accf[d];
}

extern "C" void kernel_launch(void* const* d_in, const int* in_sizes, int n_in,
                              void* d_out, int out_size)
{
    (void)in_sizes; (void)n_in; (void)out_size;
    const float* feat_l = (const float*)d_in[0];
    const float* feat_r = (const float*)d_in[1];
    const float* disp   = (const float*)d_in[2];
    float* out = (float*)d_out;

    dim3 grid(4, H_, B_);     // 2 halves x 2 d-splits = 1024 thin CTAs
    cost_volume_kernel<<<grid, WT>>>(feat_l, feat_r, disp, out);
}